// round 3
// baseline (speedup 1.0000x reference)
#include <cuda_runtime.h>
#include <math.h>

#define BZ   512
#define TM1  127
#define ENC  256
#define HS   256      // LSTM hidden
#define NBLK 128      // persistent LSTM grid

typedef unsigned long long ull;

// ---------------- device state ----------------
__device__ float g_wenc[ENC];
__device__ float g_dT[HS][BZ];          // d hidden state, transposed [h][b]
__device__ float g_ytilde[TM1][BZ];     // per-step scalar LSTM input, precomputed
__device__ float g_ctxfin[BZ];          // context · W_final[256:512]
__device__ unsigned g_bar_count;
__device__ volatile unsigned g_bar_gen;

// ---------------- kernel A: fused attention weight + barrier init ----------------
__global__ void k_prep(const float* __restrict__ W_attn1,
                       const float* __restrict__ W_attn2) {
    int j = threadIdx.x;            // 0..255
    float acc = 0.f;
    #pragma unroll 4
    for (int k = 0; k < 128; ++k)
        acc += W_attn2[k] * W_attn1[k * 768 + 512 + j];
    g_wenc[j] = acc;
    if (j == 0) { g_bar_count = 0; g_bar_gen = 0; }
}

// ---------------- kernel B: scores -> softmax -> context -> folded dots ----------------
__global__ void k_attn(const float* __restrict__ X,
                       const float* __restrict__ y_prev,
                       const float* __restrict__ W_fc,
                       const float* __restrict__ b_fc,
                       const float* __restrict__ W_final) {
    __shared__ float wenc_s[256];
    __shared__ float sc[128];
    __shared__ float red[256];
    __shared__ float red2[256];
    const int b   = blockIdx.x;
    const int tid = threadIdx.x;
    const int lane = tid & 31, warp = tid >> 5;
    wenc_s[tid] = g_wenc[tid];
    __syncthreads();

    const float* Xb = X + (size_t)b * TM1 * ENC;

    for (int t = warp; t < TM1; t += 8) {
        const float* xr = Xb + t * ENC;
        float p = 0.f;
        #pragma unroll
        for (int i = 0; i < 8; ++i)
            p += xr[lane + 32 * i] * wenc_s[lane + 32 * i];
        #pragma unroll
        for (int o = 16; o; o >>= 1) p += __shfl_down_sync(0xffffffffu, p, o);
        if (lane == 0) sc[t] = p;
    }
    __syncthreads();

    float v = (tid < TM1) ? sc[tid] : -INFINITY;
    red[tid] = v; __syncthreads();
    for (int s = 128; s; s >>= 1) {
        if (tid < s) red[tid] = fmaxf(red[tid], red[tid + s]);
        __syncthreads();
    }
    float m = red[0];
    __syncthreads();
    float e = (tid < TM1) ? __expf(v - m) : 0.f;
    red[tid] = e; __syncthreads();
    for (int s = 128; s; s >>= 1) {
        if (tid < s) red[tid] += red[tid + s];
        __syncthreads();
    }
    float inv = 1.f / red[0];
    __syncthreads();
    if (tid < TM1) sc[tid] = e * inv;
    __syncthreads();

    float ctx = 0.f;
    #pragma unroll 4
    for (int t = 0; t < TM1; ++t)
        ctx += sc[t] * Xb[t * ENC + tid];

    red[tid]  = ctx * W_fc[tid];
    red2[tid] = ctx * W_final[256 + tid];
    __syncthreads();
    for (int s = 128; s; s >>= 1) {
        if (tid < s) { red[tid] += red[tid + s]; red2[tid] += red2[tid + s]; }
        __syncthreads();
    }
    float ytc = red[0] + b_fc[0];
    if (tid == 0) g_ctxfin[b] = red2[0];

    const float wfy = W_fc[256];
    for (int t = tid; t < TM1; t += 256)
        g_ytilde[t][b] = ytc + y_prev[b * TM1 + t] * wfy;
}

// ---------------- persistent LSTM ----------------
__device__ __forceinline__ void grid_barrier() {
    __syncthreads();
    if (threadIdx.x == 0) {
        __threadfence();
        unsigned gen = g_bar_gen;
        if (atomicAdd(&g_bar_count, 1u) == NBLK - 1) {
            g_bar_count = 0;
            __threadfence();
            g_bar_gen = gen + 1;
        } else {
            while (g_bar_gen == gen) __nanosleep(64);
        }
    }
    __syncthreads();
}

__device__ __forceinline__ float sigmoidf(float x) {
    return 1.f / (1.f + __expf(-x));
}

#define FMA2(acc, w, d) asm("fma.rn.f32x2 %0, %1, %2, %0;" : "+l"(acc) : "l"(w), "l"(d))

__device__ __forceinline__ ull pack2(float lo, float hi) {
    ull u; asm("mov.b64 %0, {%1, %2};" : "=l"(u) : "f"(lo), "f"(hi)); return u;
}
__device__ __forceinline__ void unpack2(ull u, float& lo, float& hi) {
    asm("mov.b64 {%0, %1}, %2;" : "=f"(lo), "=f"(hi) : "l"(u));
}

// Block tile: 64 batches x 64 gate rows (= 16 h x 4 gates). 256 threads.
// lane -> batch pair (f32x2 packed), warp -> 8 gate rows (2 h x 4 gates).
// smem: wdup[k][r] = (w,w) duplicated pairs (weight broadcast across lanes),
//       d_s[k][b_local] compact (coalesced LDS.64 per lane).
__global__ void __launch_bounds__(256, 1) k_lstm(
    const float* __restrict__ W_hh, const float* __restrict__ W_ih,
    const float* __restrict__ b_ih, const float* __restrict__ b_hh)
{
    extern __shared__ float smem[];
    float* wdup = smem;               // [256][128] floats (64 rows x (w,w))
    float* d_s  = smem + 256 * 128;   // [256][64]  floats

    const int tid   = threadIdx.x;
    const int lane  = tid & 31;
    const int warp  = tid >> 5;
    const int bt    = blockIdx.x & 7;     // 8 batch tiles x 64
    const int rt    = blockIdx.x >> 3;    // 16 h tiles x 16
    const int bbase = bt * 64;
    const int b0    = bbase + lane * 2;   // this thread's batch pair
    const int h0    = rt * 16 + warp * 2; // this thread's 2 h values

    // ---- preload W_hh tile, duplicated (w,w), rows permuted: r = h_local*4 + gate
    for (int idx = tid; idx < 64 * 64; idx += 256) {
        int r  = idx >> 6;          // local row 0..63: h_local = r>>2, gate = r&3
        int k4 = idx & 63;
        int gate = r & 3;
        int h = rt * 16 + (r >> 2);
        float4 w = *reinterpret_cast<const float4*>(W_hh + (size_t)(gate * 256 + h) * 256 + k4 * 4);
        *reinterpret_cast<float2*>(wdup + (k4 * 4 + 0) * 128 + r * 2) = make_float2(w.x, w.x);
        *reinterpret_cast<float2*>(wdup + (k4 * 4 + 1) * 128 + r * 2) = make_float2(w.y, w.y);
        *reinterpret_cast<float2*>(wdup + (k4 * 4 + 2) * 128 + r * 2) = make_float2(w.z, w.z);
        *reinterpret_cast<float2*>(wdup + (k4 * 4 + 3) * 128 + r * 2) = make_float2(w.w, w.w);
    }

    // per-thread gate params: j = hsub*4 + gate (matches wdup row order warp*8 + j)
    float wih[8], bias[8];
    #pragma unroll
    for (int j = 0; j < 8; ++j) {
        int gate = j & 3, hsub = j >> 2;
        int row = gate * 256 + h0 + hsub;
        wih[j]  = W_ih[row];
        bias[j] = b_ih[row] + b_hh[row];
    }

    // zero my d slice; c lives in registers
    *reinterpret_cast<float2*>(&g_dT[h0][b0])     = make_float2(0.f, 0.f);
    *reinterpret_cast<float2*>(&g_dT[h0 + 1][b0]) = make_float2(0.f, 0.f);
    float c_reg[2][2] = {{0.f, 0.f}, {0.f, 0.f}};

    grid_barrier();

    const float* dsp = d_s + lane * 2;
    const float* wsp = wdup + warp * 16;

    for (int t = 0; t < TM1; ++t) {
        // load d tile [256 k][64 b] from global (cross-SM -> L2)
        #pragma unroll
        for (int i = 0; i < 16; ++i) {
            int ii = tid + i * 256;
            int k = ii >> 4, c4 = ii & 15;
            float4 dv = __ldcg(reinterpret_cast<const float4*>(&g_dT[k][bbase + c4 * 4]));
            *reinterpret_cast<float4*>(&d_s[k * 64 + c4 * 4]) = dv;
        }
        __syncthreads();

        float2 yt = *reinterpret_cast<const float2*>(&g_ytilde[t][b0]);
        ull acc[8];
        #pragma unroll
        for (int j = 0; j < 8; ++j)
            acc[j] = pack2(fmaf(yt.x, wih[j], bias[j]), fmaf(yt.y, wih[j], bias[j]));

        #pragma unroll 4
        for (int k = 0; k < 256; ++k) {
            ull dp = *reinterpret_cast<const ull*>(dsp + k * 64);
            ulonglong2 wa = *reinterpret_cast<const ulonglong2*>(wsp + k * 128);
            ulonglong2 wb = *reinterpret_cast<const ulonglong2*>(wsp + k * 128 + 4);
            ulonglong2 wc = *reinterpret_cast<const ulonglong2*>(wsp + k * 128 + 8);
            ulonglong2 wd = *reinterpret_cast<const ulonglong2*>(wsp + k * 128 + 12);
            FMA2(acc[0], wa.x, dp);
            FMA2(acc[1], wa.y, dp);
            FMA2(acc[2], wb.x, dp);
            FMA2(acc[3], wb.y, dp);
            FMA2(acc[4], wc.x, dp);
            FMA2(acc[5], wc.y, dp);
            FMA2(acc[6], wd.x, dp);
            FMA2(acc[7], wd.y, dp);
        }

        float a[8][2];
        #pragma unroll
        for (int j = 0; j < 8; ++j) unpack2(acc[j], a[j][0], a[j][1]);

        #pragma unroll
        for (int hs = 0; hs < 2; ++hs) {
            float2 dn;
            float* dnp = &dn.x;
            #pragma unroll
            for (int bb = 0; bb < 2; ++bb) {
                float ig = sigmoidf(a[hs * 4 + 0][bb]);
                float fg = sigmoidf(a[hs * 4 + 1][bb]);
                float gg = tanhf(a[hs * 4 + 2][bb]);
                float og = sigmoidf(a[hs * 4 + 3][bb]);
                float cn = fg * c_reg[hs][bb] + ig * gg;
                c_reg[hs][bb] = cn;
                dnp[bb] = og * tanhf(cn);
            }
            *reinterpret_cast<float2*>(&g_dT[h0 + hs][b0]) = dn;
        }

        grid_barrier();
    }
}

// ---------------- final projection ----------------
__global__ void k_final(const float* __restrict__ W_final,
                        const float* __restrict__ b_final,
                        float* __restrict__ out) {
    int b = blockIdx.x * 8 + (threadIdx.x >> 5);
    int lane = threadIdx.x & 31;
    float acc = 0.f;
    #pragma unroll
    for (int i = 0; i < 8; ++i) {
        int hh = lane + 32 * i;
        acc += g_dT[hh][b] * W_final[hh];
    }
    #pragma unroll
    for (int o = 16; o; o >>= 1) acc += __shfl_down_sync(0xffffffffu, acc, o);
    if (lane == 0) out[b] = acc + g_ctxfin[b] + b_final[0];
}

// ---------------- launch ----------------
extern "C" void kernel_launch(void* const* d_in, const int* in_sizes, int n_in,
                              void* d_out, int out_size) {
    const float* X       = (const float*)d_in[0];
    const float* y_prev  = (const float*)d_in[1];
    const float* W_attn1 = (const float*)d_in[2];
    const float* W_attn2 = (const float*)d_in[4];
    const float* W_fc    = (const float*)d_in[6];
    const float* b_fc    = (const float*)d_in[7];
    const float* W_ih    = (const float*)d_in[8];
    const float* W_hh    = (const float*)d_in[9];
    const float* b_ih    = (const float*)d_in[10];
    const float* b_hh    = (const float*)d_in[11];
    const float* W_final = (const float*)d_in[12];
    const float* b_final = (const float*)d_in[13];
    float* out = (float*)d_out;

    const int smem_bytes = (256 * 128 + 256 * 64) * sizeof(float);   // 196608
    cudaFuncSetAttribute(k_lstm, cudaFuncAttributeMaxDynamicSharedMemorySize, smem_bytes);

    k_prep<<<1, 256>>>(W_attn1, W_attn2);
    k_attn<<<BZ, 256>>>(X, y_prev, W_fc, b_fc, W_final);
    k_lstm<<<NBLK, 256, smem_bytes>>>(W_hh, W_ih, b_ih, b_hh);
    k_final<<<BZ / 8, 256>>>(W_final, b_final, out);
}

// round 4
// speedup vs baseline: 2.0209x; 2.0209x over previous
#include <cuda_runtime.h>
#include <cuda_bf16.h>
#include <math.h>

#define BZ   512
#define TM1  127
#define NBLK 128

#define LDK      264                    // bf16 row stride (528B) for W/d smem tiles
#define WTILE_B  (64 * LDK * 2)         // 33792 bytes per split tile
#define PRE_LD   66

typedef unsigned int uint32;

// ---------------- device state ----------------
__device__ float g_wenc[256];
__device__ __nv_bfloat16 g_dhi[16 * 512 * 16];   // [gate-tile][batch][16 h] slabs
__device__ __nv_bfloat16 g_dlo[16 * 512 * 16];
__device__ float g_ytilde[TM1][BZ];
__device__ float g_ctxfin[BZ];
__device__ unsigned g_bar_count;
__device__ volatile unsigned g_bar_gen;

// ---------------- kernel A: fused attention weight + barrier init ----------------
__global__ void k_prep(const float* __restrict__ W_attn1,
                       const float* __restrict__ W_attn2) {
    int j = threadIdx.x;
    float acc = 0.f;
    #pragma unroll 4
    for (int k = 0; k < 128; ++k)
        acc += W_attn2[k] * W_attn1[k * 768 + 512 + j];
    g_wenc[j] = acc;
    if (j == 0) { g_bar_count = 0; g_bar_gen = 0; }
}

// ---------------- kernel B: scores -> softmax -> context -> folded dots ----------------
__global__ void k_attn(const float* __restrict__ X,
                       const float* __restrict__ y_prev,
                       const float* __restrict__ W_fc,
                       const float* __restrict__ b_fc,
                       const float* __restrict__ W_final) {
    __shared__ float wenc_s[256];
    __shared__ float sc[128];
    __shared__ float red[256];
    __shared__ float red2[256];
    const int b   = blockIdx.x;
    const int tid = threadIdx.x;
    const int lane = tid & 31, warp = tid >> 5;
    wenc_s[tid] = g_wenc[tid];
    __syncthreads();

    const float* Xb = X + (size_t)b * TM1 * 256;

    for (int t = warp; t < TM1; t += 8) {
        const float* xr = Xb + t * 256;
        float p = 0.f;
        #pragma unroll
        for (int i = 0; i < 8; ++i)
            p += xr[lane + 32 * i] * wenc_s[lane + 32 * i];
        #pragma unroll
        for (int o = 16; o; o >>= 1) p += __shfl_down_sync(0xffffffffu, p, o);
        if (lane == 0) sc[t] = p;
    }
    __syncthreads();

    float v = (tid < TM1) ? sc[tid] : -INFINITY;
    red[tid] = v; __syncthreads();
    for (int s = 128; s; s >>= 1) {
        if (tid < s) red[tid] = fmaxf(red[tid], red[tid + s]);
        __syncthreads();
    }
    float m = red[0];
    __syncthreads();
    float e = (tid < TM1) ? __expf(v - m) : 0.f;
    red[tid] = e; __syncthreads();
    for (int s = 128; s; s >>= 1) {
        if (tid < s) red[tid] += red[tid + s];
        __syncthreads();
    }
    float inv = 1.f / red[0];
    __syncthreads();
    if (tid < TM1) sc[tid] = e * inv;
    __syncthreads();

    float ctx = 0.f;
    #pragma unroll 4
    for (int t = 0; t < TM1; ++t)
        ctx += sc[t] * Xb[t * 256 + tid];

    red[tid]  = ctx * W_fc[tid];
    red2[tid] = ctx * W_final[256 + tid];
    __syncthreads();
    for (int s = 128; s; s >>= 1) {
        if (tid < s) { red[tid] += red[tid + s]; red2[tid] += red2[tid + s]; }
        __syncthreads();
    }
    float ytc = red[0] + b_fc[0];
    if (tid == 0) g_ctxfin[b] = red2[0];

    const float wfy = W_fc[256];
    for (int t = tid; t < TM1; t += 256)
        g_ytilde[t][b] = ytc + y_prev[b * TM1 + t] * wfy;
}

// ---------------- helpers ----------------
__device__ __forceinline__ void grid_barrier() {
    __syncthreads();
    if (threadIdx.x == 0) {
        __threadfence();
        unsigned gen = g_bar_gen;
        if (atomicAdd(&g_bar_count, 1u) == NBLK - 1) {
            g_bar_count = 0;
            __threadfence();
            g_bar_gen = gen + 1;
        } else {
            while (g_bar_gen == gen) __nanosleep(64);
        }
    }
    __syncthreads();
}

__device__ __forceinline__ float sigmoidf(float x) {
    return 1.f / (1.f + __expf(-x));
}

__device__ __forceinline__ uint32 smem_u32(const void* p) {
    uint32 a;
    asm("{ .reg .u64 t; cvta.to.shared.u64 t, %1; cvt.u32.u64 %0, t; }" : "=r"(a) : "l"(p));
    return a;
}

#define LDSM4(r0, r1, r2, r3, addr) \
    asm volatile("ldmatrix.sync.aligned.m8n8.x4.shared.b16 {%0,%1,%2,%3}, [%4];" \
                 : "=r"(r0), "=r"(r1), "=r"(r2), "=r"(r3) : "r"(addr))

#define MMA16816(c, a, b0, b1) \
    asm volatile("mma.sync.aligned.m16n8k16.row.col.f32.bf16.bf16.f32 " \
                 "{%0,%1,%2,%3}, {%4,%5,%6,%7}, {%8,%9}, {%0,%1,%2,%3};" \
                 : "+f"(c[0]), "+f"(c[1]), "+f"(c[2]), "+f"(c[3]) \
                 : "r"(a[0]), "r"(a[1]), "r"(a[2]), "r"(a[3]), "r"(b0), "r"(b1))

// ---------------- persistent LSTM, tensor-core 3xBF16 ----------------
// smem byte offsets
#define OFF_WHI   0
#define OFF_WLO   (OFF_WHI + WTILE_B)          // 33792
#define OFF_DHI   (OFF_WLO + WTILE_B)          // 67584
#define OFF_DLO   (OFF_DHI + WTILE_B)          // 101376
#define OFF_PRE   (OFF_DLO + WTILE_B)          // 135168
#define OFF_STHI  (OFF_PRE + 64 * PRE_LD * 4)  // 152064
#define OFF_STLO  (OFF_STHI + 2048)            // 154112
#define OFF_WIHB  (OFF_STLO + 2048)            // 156160
#define OFF_BIAS  (OFF_WIHB + 256)             // 156416
#define SMEM_LSTM (OFF_BIAS + 256)             // 156672

__global__ void __launch_bounds__(256, 1) k_lstm(
    const float* __restrict__ W_hh, const float* __restrict__ W_ih,
    const float* __restrict__ b_ih, const float* __restrict__ b_hh)
{
    extern __shared__ char smem[];
    __nv_bfloat16* Whi  = (__nv_bfloat16*)(smem + OFF_WHI);
    __nv_bfloat16* Wlo  = (__nv_bfloat16*)(smem + OFF_WLO);
    __nv_bfloat16* Dhi  = (__nv_bfloat16*)(smem + OFF_DHI);
    __nv_bfloat16* Dlo  = (__nv_bfloat16*)(smem + OFF_DLO);
    float*         pre  = (float*)(smem + OFF_PRE);
    __nv_bfloat16* sthi = (__nv_bfloat16*)(smem + OFF_STHI);
    __nv_bfloat16* stlo = (__nv_bfloat16*)(smem + OFF_STLO);
    float*         wihb = (float*)(smem + OFF_WIHB);
    float*         bias = (float*)(smem + OFF_BIAS);

    const int tid  = threadIdx.x;
    const int lane = tid & 31;
    const int warp = tid >> 5;
    const int bt    = blockIdx.x & 7;      // batch tile (64)
    const int gt    = blockIdx.x >> 3;     // gate-row tile (64 rows = 16 h x 4 gates)
    const int bbase = bt * 64;

    // ---- preload W tile, split into bf16 hi/lo, rows r = h_local*4 + gate ----
    for (int idx = tid; idx < 64 * 64; idx += 256) {
        int r = idx >> 6, c4 = idx & 63;
        int gate = r & 3, h = gt * 16 + (r >> 2);
        float4 w = *(const float4*)(W_hh + (size_t)(gate * 256 + h) * 256 + c4 * 4);
        float wv[4] = {w.x, w.y, w.z, w.w};
        #pragma unroll
        for (int j = 0; j < 4; ++j) {
            __nv_bfloat16 hi = __float2bfloat16(wv[j]);
            __nv_bfloat16 lo = __float2bfloat16(wv[j] - __bfloat162float(hi));
            Whi[r * LDK + c4 * 4 + j] = hi;
            Wlo[r * LDK + c4 * 4 + j] = lo;
        }
    }
    if (tid < 64) {
        int gate = tid & 3, h = gt * 16 + (tid >> 2);
        int row = gate * 256 + h;
        wihb[tid] = W_ih[row];
        bias[tid] = b_ih[row] + b_hh[row];
    }

    // ---- zero my global d slab (rows gt*512+bbase .. +64, 16 bf16 each) ----
    {
        uint4 z = make_uint4(0, 0, 0, 0);
        uint4* ghi = (uint4*)g_dhi + (size_t)(gt * 512 + bbase) * 2;
        uint4* glo = (uint4*)g_dlo + (size_t)(gt * 512 + bbase) * 2;
        if (tid < 128) ghi[tid] = z;
        else           glo[tid - 128] = z;
    }

    // ---- per-warp MMA geometry: 4 m-tiles x 2 n-tiles ----
    const int wm = warp & 3;           // m16 tile
    const int wn = warp >> 2;          // n32 tile
    const uint32 sb = smem_u32(smem);

    const uint32 aHi = sb + OFF_WHI +
        (((wm * 16 + (lane & 15)) * LDK + ((lane >> 4) * 8)) * 2);
    const uint32 aLo = aHi + WTILE_B;

    const int bRow = wn * 32 + ((lane >> 4) << 3) + (lane & 7);
    const int bCol = ((lane >> 3) & 1) * 8;
    const uint32 bHi0 = sb + OFF_DHI + ((bRow * LDK + bCol) * 2);
    const uint32 bHi1 = bHi0 + 16 * LDK * 2;
    const uint32 bLo0 = bHi0 + WTILE_B;
    const uint32 bLo1 = bHi1 + WTILE_B;

    // epilogue ownership: thread -> (b_local, 4 h values)
    const int b_local = tid & 63;
    const int hq = tid >> 6;
    float c_reg[4] = {0.f, 0.f, 0.f, 0.f};

    grid_barrier();

    for (int t = 0; t < TM1; ++t) {
        // ---- load d tile (hi/lo) global -> smem, slab layout ----
        #pragma unroll
        for (int i = 0; i < 8; ++i) {
            int idx  = tid + i * 256;          // 0..2047
            int ck   = idx >> 7;
            int rem  = idx & 127;
            int b    = rem >> 1;
            int half = rem & 1;
            size_t gidx = (size_t)(ck * 512 + bbase + b) * 2 + half;
            uint4 vh = __ldcg((const uint4*)g_dhi + gidx);
            uint4 vl = __ldcg((const uint4*)g_dlo + gidx);
            *(uint4*)(Dhi + b * LDK + ck * 16 + half * 8) = vh;
            *(uint4*)(Dlo + b * LDK + ck * 16 + half * 8) = vl;
        }
        __syncthreads();

        // ---- MMA: acc[j] = sum_k Whi*dhi + Whi*dlo + Wlo*dhi ----
        float acc[4][4];
        #pragma unroll
        for (int j = 0; j < 4; ++j)
            #pragma unroll
            for (int r = 0; r < 4; ++r) acc[j][r] = 0.f;

        #pragma unroll
        for (int ck = 0; ck < 16; ++ck) {
            const uint32 ko = ck * 32;         // 16 bf16 = 32 bytes
            uint32 ah[4], al[4], bh[8], bl[8];
            LDSM4(ah[0], ah[1], ah[2], ah[3], aHi + ko);
            LDSM4(al[0], al[1], al[2], al[3], aLo + ko);
            LDSM4(bh[0], bh[1], bh[2], bh[3], bHi0 + ko);
            LDSM4(bh[4], bh[5], bh[6], bh[7], bHi1 + ko);
            LDSM4(bl[0], bl[1], bl[2], bl[3], bLo0 + ko);
            LDSM4(bl[4], bl[5], bl[6], bl[7], bLo1 + ko);
            #pragma unroll
            for (int j = 0; j < 4; ++j) MMA16816(acc[j], ah, bh[2 * j], bh[2 * j + 1]);
            #pragma unroll
            for (int j = 0; j < 4; ++j) MMA16816(acc[j], ah, bl[2 * j], bl[2 * j + 1]);
            #pragma unroll
            for (int j = 0; j < 4; ++j) MMA16816(acc[j], al, bh[2 * j], bh[2 * j + 1]);
        }

        // ---- dump accumulators to smem preact[m][n] ----
        {
            const int mrow = wm * 16 + (lane >> 2);
            const int ncol = wn * 32 + (lane & 3) * 2;
            #pragma unroll
            for (int j = 0; j < 4; ++j) {
                *(float2*)&pre[mrow * PRE_LD + ncol + j * 8]       = make_float2(acc[j][0], acc[j][1]);
                *(float2*)&pre[(mrow + 8) * PRE_LD + ncol + j * 8] = make_float2(acc[j][2], acc[j][3]);
            }
        }
        __syncthreads();

        // ---- LSTM cell update: thread owns (b_local, h = hq*4 + 0..3) ----
        {
            float ytv = g_ytilde[t][bbase + b_local];
            #pragma unroll
            for (int hi_ = 0; hi_ < 4; ++hi_) {
                int hl = hq * 4 + hi_;
                float p0 = pre[(hl * 4 + 0) * PRE_LD + b_local] + ytv * wihb[hl * 4 + 0] + bias[hl * 4 + 0];
                float p1 = pre[(hl * 4 + 1) * PRE_LD + b_local] + ytv * wihb[hl * 4 + 1] + bias[hl * 4 + 1];
                float p2 = pre[(hl * 4 + 2) * PRE_LD + b_local] + ytv * wihb[hl * 4 + 2] + bias[hl * 4 + 2];
                float p3 = pre[(hl * 4 + 3) * PRE_LD + b_local] + ytv * wihb[hl * 4 + 3] + bias[hl * 4 + 3];
                float ig = sigmoidf(p0);
                float fg = sigmoidf(p1);
                float gg = tanhf(p2);
                float og = sigmoidf(p3);
                float cn = fg * c_reg[hi_] + ig * gg;
                c_reg[hi_] = cn;
                float d = og * tanhf(cn);
                __nv_bfloat16 dh = __float2bfloat16(d);
                __nv_bfloat16 dl = __float2bfloat16(d - __bfloat162float(dh));
                sthi[b_local * 16 + hl] = dh;
                stlo[b_local * 16 + hl] = dl;
            }
        }
        __syncthreads();

        // ---- coalesced write of my slab to global ----
        if (tid < 64) {
            uint4* dst = (uint4*)g_dhi + (size_t)(gt * 512 + bbase + tid) * 2;
            uint4* src = (uint4*)(sthi + tid * 16);
            dst[0] = src[0]; dst[1] = src[1];
            __threadfence();
        } else if (tid < 128) {
            int r = tid - 64;
            uint4* dst = (uint4*)g_dlo + (size_t)(gt * 512 + bbase + r) * 2;
            uint4* src = (uint4*)(stlo + r * 16);
            dst[0] = src[0]; dst[1] = src[1];
            __threadfence();
        }

        grid_barrier();
    }
}

// ---------------- final projection ----------------
__global__ void k_final(const float* __restrict__ W_final,
                        const float* __restrict__ b_final,
                        float* __restrict__ out) {
    int b = blockIdx.x * 8 + (threadIdx.x >> 5);
    int lane = threadIdx.x & 31;
    float acc = 0.f;
    #pragma unroll
    for (int i = 0; i < 8; ++i) {
        int h = lane + 32 * i;
        size_t idx = (size_t)((h >> 4) * 512 + b) * 16 + (h & 15);
        float d = __bfloat162float(g_dhi[idx]) + __bfloat162float(g_dlo[idx]);
        acc += d * W_final[h];
    }
    #pragma unroll
    for (int o = 16; o; o >>= 1) acc += __shfl_down_sync(0xffffffffu, acc, o);
    if (lane == 0) out[b] = acc + g_ctxfin[b] + b_final[0];
}

// ---------------- launch ----------------
extern "C" void kernel_launch(void* const* d_in, const int* in_sizes, int n_in,
                              void* d_out, int out_size) {
    const float* X       = (const float*)d_in[0];
    const float* y_prev  = (const float*)d_in[1];
    const float* W_attn1 = (const float*)d_in[2];
    const float* W_attn2 = (const float*)d_in[4];
    const float* W_fc    = (const float*)d_in[6];
    const float* b_fc    = (const float*)d_in[7];
    const float* W_ih    = (const float*)d_in[8];
    const float* W_hh    = (const float*)d_in[9];
    const float* b_ih    = (const float*)d_in[10];
    const float* b_hh    = (const float*)d_in[11];
    const float* W_final = (const float*)d_in[12];
    const float* b_final = (const float*)d_in[13];
    float* out = (float*)d_out;

    cudaFuncSetAttribute(k_lstm, cudaFuncAttributeMaxDynamicSharedMemorySize, SMEM_LSTM);

    k_prep<<<1, 256>>>(W_attn1, W_attn2);
    k_attn<<<BZ, 256>>>(X, y_prev, W_fc, b_fc, W_final);
    k_lstm<<<NBLK, 256, SMEM_LSTM>>>(W_hh, W_ih, b_ih, b_hh);
    k_final<<<BZ / 8, 256>>>(W_final, b_final, out);
}